// round 10
// baseline (speedup 1.0000x reference)
#include <cuda_runtime.h>
#include <cuda_bf16.h>
#include <cstdint>

#define DEVI static __device__ __forceinline__

static constexpr int MT = 64 * 197;   // 12608 rows
static constexpr int DD = 768;
static constexpr int HH = 3072;
static constexpr float FBIG = 3.0e38f;

// exact-divisible elementwise grids (256 threads/block)
// n4_x = MT*DD/4 = 2,420,736 = (1182*256)*8
// n4_w = HH*DD/4 =   589,824 = (288*256)*8
// n4_g = MT*HH/4 = 9,682,944 = (4728*256)*8
static constexpr int XB = 1182, WB = 288, GB = 4728;

// Scratch (allocation-free rule: __device__ globals)
__device__ __nv_bfloat16 g_xq[MT * DD];
__device__ __nv_bfloat16 g_w1q[HH * DD];
__device__ __nv_bfloat16 g_w2q[DD * HH];
__device__ float         g_mid[(size_t)MT * HH];
__device__ __nv_bfloat16 g_gq[(size_t)MT * HH];
__device__ float         g_stats[6];             // xmin,xmax,w1max,w2max,gmin,gmax

DEVI void atomicMinF(float* a, float v) {
    int* ai = (int*)a;
    int old = *ai;
    while (__int_as_float(old) > v) {
        int as = old;
        old = atomicCAS(ai, as, __float_as_int(v));
        if (old == as) break;
    }
}
DEVI void atomicMaxF(float* a, float v) {
    int* ai = (int*)a;
    int old = *ai;
    while (__int_as_float(old) < v) {
        int as = old;
        old = atomicCAS(ai, as, __float_as_int(v));
        if (old == as) break;
    }
}

__global__ void k_init() {
    g_stats[0] = FBIG;  g_stats[1] = -FBIG;
    g_stats[2] = 0.f;   g_stats[3] = 0.f;
    g_stats[4] = FBIG;  g_stats[5] = -FBIG;
}

// ---- fused stats, MLP=4 unrolled grid-stride, exact grids ----
// blocks [0,XB) minmax(x), [XB,XB+WB) absmax(w1), [XB+WB,XB+2WB) absmax(w2)
__global__ void k_stats(const float* __restrict__ x, const float* __restrict__ w1,
                        const float* __restrict__ w2) {
    int b = blockIdx.x;
    const float4* src;
    int n4, st, bb, mode, sidx;
    if (b < XB)           { src = (const float4*)x;  n4 = MT * DD / 4; st = XB * 256; bb = b;            mode = 0; sidx = 0; }
    else if (b < XB + WB) { src = (const float4*)w1; n4 = HH * DD / 4; st = WB * 256; bb = b - XB;       mode = 1; sidx = 2; }
    else                  { src = (const float4*)w2; n4 = DD * HH / 4; st = WB * 256; bb = b - XB - WB;  mode = 1; sidx = 3; }

    float lo = FBIG, hi = -FBIG;
    int i = bb * 256 + threadIdx.x;
    for (int o = 0; o < n4; o += 4 * st) {
        float4 a = src[i + o];
        float4 c = src[i + o + st];
        float4 d = src[i + o + 2 * st];
        float4 e = src[i + o + 3 * st];
        if (mode == 0) {
            lo = fminf(lo, fminf(fminf(fminf(a.x, a.y), fminf(a.z, a.w)),
                                 fminf(fminf(c.x, c.y), fminf(c.z, c.w))));
            lo = fminf(lo, fminf(fminf(fminf(d.x, d.y), fminf(d.z, d.w)),
                                 fminf(fminf(e.x, e.y), fminf(e.z, e.w))));
            hi = fmaxf(hi, fmaxf(fmaxf(fmaxf(a.x, a.y), fmaxf(a.z, a.w)),
                                 fmaxf(fmaxf(c.x, c.y), fmaxf(c.z, c.w))));
            hi = fmaxf(hi, fmaxf(fmaxf(fmaxf(d.x, d.y), fmaxf(d.z, d.w)),
                                 fmaxf(fmaxf(e.x, e.y), fmaxf(e.z, e.w))));
        } else {
            hi = fmaxf(hi, fmaxf(fmaxf(fmaxf(fabsf(a.x), fabsf(a.y)), fmaxf(fabsf(a.z), fabsf(a.w))),
                                 fmaxf(fmaxf(fabsf(c.x), fabsf(c.y)), fmaxf(fabsf(c.z), fabsf(c.w)))));
            hi = fmaxf(hi, fmaxf(fmaxf(fmaxf(fabsf(d.x), fabsf(d.y)), fmaxf(fabsf(d.z), fabsf(d.w))),
                                 fmaxf(fmaxf(fabsf(e.x), fabsf(e.y)), fmaxf(fabsf(e.z), fabsf(e.w)))));
        }
    }
    for (int o = 16; o; o >>= 1) {
        lo = fminf(lo, __shfl_xor_sync(0xffffffffu, lo, o));
        hi = fmaxf(hi, __shfl_xor_sync(0xffffffffu, hi, o));
    }
    __shared__ float slo[8], shi[8];
    int w = threadIdx.x >> 5;
    if ((threadIdx.x & 31) == 0) { slo[w] = lo; shi[w] = hi; }
    __syncthreads();
    if (threadIdx.x == 0) {
        for (int k = 1; k < 8; k++) { lo = fminf(lo, slo[k]); hi = fmaxf(hi, shi[k]); }
        if (mode == 0) { atomicMinF(&g_stats[0], lo); atomicMaxF(&g_stats[1], hi); }
        else           { atomicMaxF(&g_stats[sidx], hi); }
    }
}

DEVI float quant_act_one(float v, float s, float zp) {
    return fminf(fmaxf(rintf(v / s) + zp, 0.f), 255.f) - zp;
}
DEVI uint2 quant_act4(float4 v, float s, float zp) {
    __nv_bfloat162 lo = __floats2bfloat162_rn(quant_act_one(v.x, s, zp), quant_act_one(v.y, s, zp));
    __nv_bfloat162 hi = __floats2bfloat162_rn(quant_act_one(v.z, s, zp), quant_act_one(v.w, s, zp));
    uint2 r;
    r.x = *(uint32_t*)&lo;
    r.y = *(uint32_t*)&hi;
    return r;
}
DEVI uint2 quant_w4(float4 v, float s) {
    float q0 = fminf(fmaxf(rintf(v.x / s), -128.f), 127.f);
    float q1 = fminf(fmaxf(rintf(v.y / s), -128.f), 127.f);
    float q2 = fminf(fmaxf(rintf(v.z / s), -128.f), 127.f);
    float q3 = fminf(fmaxf(rintf(v.w / s), -128.f), 127.f);
    __nv_bfloat162 lo = __floats2bfloat162_rn(q0, q1);
    __nv_bfloat162 hi = __floats2bfloat162_rn(q2, q3);
    uint2 r;
    r.x = *(uint32_t*)&lo;
    r.y = *(uint32_t*)&hi;
    return r;
}

// ---- fused quant, MLP=4, exact grids; layout mirrors k_stats ----
__global__ void k_quant(const float* __restrict__ x, const float* __restrict__ w1,
                        const float* __restrict__ w2) {
    int b = blockIdx.x;
    if (b < XB) {
        float lo = g_stats[0], hi = g_stats[1];
        float s = fmaxf(hi - lo, 1e-8f) / 255.0f;
        float zp = rintf(-lo / s);
        const float4* src = (const float4*)x;
        uint2* qp = (uint2*)g_xq;
        int n4 = MT * DD / 4, st = XB * 256;
        int i = b * 256 + threadIdx.x;
        for (int o = 0; o < n4; o += 4 * st) {
            float4 a = src[i + o];
            float4 c = src[i + o + st];
            float4 d = src[i + o + 2 * st];
            float4 e = src[i + o + 3 * st];
            qp[i + o]          = quant_act4(a, s, zp);
            qp[i + o + st]     = quant_act4(c, s, zp);
            qp[i + o + 2 * st] = quant_act4(d, s, zp);
            qp[i + o + 3 * st] = quant_act4(e, s, zp);
        }
    } else {
        int which = (b >= XB + WB);
        const float4* src = (const float4*)(which ? w2 : w1);
        float s = fmaxf(g_stats[which ? 3 : 2], 1e-8f) / 127.0f;
        uint2* qp = (uint2*)(which ? g_w2q : g_w1q);
        int bb = b - XB - (which ? WB : 0);
        int n4 = HH * DD / 4, st = WB * 256;
        int i = bb * 256 + threadIdx.x;
        for (int o = 0; o < n4; o += 4 * st) {
            float4 a = src[i + o];
            float4 c = src[i + o + st];
            float4 d = src[i + o + 2 * st];
            float4 e = src[i + o + 3 * st];
            qp[i + o]          = quant_w4(a, s);
            qp[i + o + st]     = quant_w4(c, s);
            qp[i + o + 2 * st] = quant_w4(d, s);
            qp[i + o + 3 * st] = quant_w4(e, s);
        }
    }
}

__global__ void k_quant_g() {
    float lo = g_stats[4], hi = g_stats[5];
    float s = fmaxf(hi - lo, 1e-8f) / 255.0f;
    float zp = rintf(-lo / s);
    uint2* qp = (uint2*)g_gq;
    const float4* src = (const float4*)g_mid;
    constexpr int n4 = (int)((size_t)MT * HH / 4);
    constexpr int st = GB * 256;
    int i = blockIdx.x * 256 + threadIdx.x;
    for (int o = 0; o < n4; o += 4 * st) {
        float4 a = __ldcs(src + i + o);
        float4 c = __ldcs(src + i + o + st);
        float4 d = __ldcs(src + i + o + 2 * st);
        float4 e = __ldcs(src + i + o + 3 * st);
        qp[i + o]          = quant_act4(a, s, zp);
        qp[i + o + st]     = quant_act4(c, s, zp);
        qp[i + o + 2 * st] = quant_act4(d, s, zp);
        qp[i + o + 3 * st] = quant_act4(e, s, zp);
    }
}

DEVI float igelu(float x) {
    float tt = x * 0.70710678118654752440f;
    float at = fminf(fabsf(tt), 1.769f);
    float dd = at - 1.769f;
    float L = fmaf(-0.2888f, dd * dd, 1.0f);
    L = copysignf(L, tt);
    return x * 0.5f * (1.0f + L);
}

DEVI void ldsm_x4(uint32_t& r0, uint32_t& r1, uint32_t& r2, uint32_t& r3, uint32_t addr) {
    asm volatile("ldmatrix.sync.aligned.m8n8.x4.shared.b16 {%0,%1,%2,%3}, [%4];"
                 : "=r"(r0), "=r"(r1), "=r"(r2), "=r"(r3) : "r"(addr));
}
DEVI void hmma(float* c, const uint32_t* a, const uint32_t* b) {
    asm volatile(
        "mma.sync.aligned.m16n8k16.row.col.f32.bf16.bf16.f32 "
        "{%0,%1,%2,%3}, {%4,%5,%6,%7}, {%8,%9}, {%0,%1,%2,%3};\n"
        : "+f"(c[0]), "+f"(c[1]), "+f"(c[2]), "+f"(c[3])
        : "r"(a[0]), "r"(a[1]), "r"(a[2]), "r"(a[3]), "r"(b[0]), "r"(b[1]));
}

// ---------------------------------------------------------------------------
// bf16 GEMM (R7 config — best measured): BM=128, BN=128, BK=64, 256 threads,
// 2 CTA/SM, 3-stage cp.async ring, single __syncthreads per iteration.
// ---------------------------------------------------------------------------
template <int EPI>
__global__ void __launch_bounds__(256, 2) k_gemm_bf(const float* __restrict__ bias,
                                                    float* __restrict__ Cout) {
    constexpr int Mn = MT;
    constexpr int Nn = (EPI == 1) ? HH : DD;
    constexpr int Kn = (EPI == 1) ? DD : HH;
    constexpr int BM = 128, BN = 128, BK = 64;
    constexpr int KT = Kn / BK;
    constexpr uint32_t STAGE = (BM + BN) * 128;   // 32 KB

    const __nv_bfloat16* __restrict__ A = (EPI == 1) ? g_xq : g_gq;
    const __nv_bfloat16* __restrict__ B = (EPI == 1) ? g_w1q : g_w2q;
    float* __restrict__ C = (EPI == 1) ? g_mid : Cout;

    extern __shared__ char smem[];
    const uint32_t sbase = (uint32_t)__cvta_generic_to_shared(smem);

    const int tid = threadIdx.x;
    const int warp = tid >> 5, lane = tid & 31;
    const int wm = warp & 1, wn = warp >> 1;      // 2x4 warps, warp tile 64x32
    const int g = lane >> 2, t = lane & 3;
    const int mBase = blockIdx.x * BM, nBase = blockIdx.y * BN;

    float acc[4][4][4];
#pragma unroll
    for (int i = 0; i < 4; i++)
#pragma unroll
        for (int j = 0; j < 4; j++)
#pragma unroll
            for (int k = 0; k < 4; k++) acc[i][j][k] = 0.f;

    auto issue = [&](int s) {
        uint32_t sb = sbase + (uint32_t)(s % 3) * STAGE;
        const int kOff = s * BK;
#pragma unroll
        for (int ci = tid; ci < 2048; ci += 256) {
            int row = ci >> 3, c = ci & 7;
            uint32_t dst = sb + (uint32_t)(row * 128 + ((c ^ (row & 7)) << 4));
            if (row < BM) {
                int grow = mBase + row;
                bool ok = grow < Mn;
                int safe = ok ? grow : (Mn - 1);
                const __nv_bfloat16* gp = A + (size_t)safe * Kn + kOff + c * 8;
                int sz = ok ? 16 : 0;
                asm volatile("cp.async.cg.shared.global [%0], [%1], 16, %2;\n"
                             :: "r"(dst), "l"(gp), "r"(sz));
            } else {
                const __nv_bfloat16* gp = B + (size_t)(nBase + row - BM) * Kn + kOff + c * 8;
                asm volatile("cp.async.cg.shared.global [%0], [%1], 16, %2;\n"
                             :: "r"(dst), "l"(gp), "r"(16));
            }
        }
        asm volatile("cp.async.commit_group;\n");
    };

    auto compute = [&](int s) {
        uint32_t sa = sbase + (uint32_t)(s % 3) * STAGE;
        uint32_t sb = sa + (uint32_t)(BM * 128);
#pragma unroll
        for (int ks = 0; ks < 4; ks++) {
            uint32_t a[4][4], b[4][2];
#pragma unroll
            for (int i = 0; i < 4; i++) {
                int row = wm * 64 + i * 16 + (lane & 15);
                int chunk = 2 * ks + (lane >> 4);
                uint32_t addr = sa + (uint32_t)(row * 128 + ((chunk ^ (row & 7)) << 4));
                ldsm_x4(a[i][0], a[i][1], a[i][2], a[i][3], addr);
            }
#pragma unroll
            for (int jp = 0; jp < 2; jp++) {
                int q = lane >> 3;
                int nrow = wn * 32 + jp * 16 + (q >> 1) * 8 + (lane & 7);
                int chunk = 2 * ks + (q & 1);
                uint32_t addr = sb + (uint32_t)(nrow * 128 + ((chunk ^ (nrow & 7)) << 4));
                ldsm_x4(b[2 * jp][0], b[2 * jp][1], b[2 * jp + 1][0], b[2 * jp + 1][1], addr);
            }
#pragma unroll
            for (int i = 0; i < 4; i++)
#pragma unroll
                for (int j = 0; j < 4; j++) hmma(acc[i][j], a[i], b[j]);
        }
    };

    issue(0);
    issue(1);
    for (int kt = 0; kt < KT; kt++) {
        if (kt + 1 < KT) asm volatile("cp.async.wait_group 1;\n" ::: "memory");
        else             asm volatile("cp.async.wait_group 0;\n" ::: "memory");
        __syncthreads();
        if (kt + 2 < KT) issue(kt + 2);
        compute(kt);
    }

    // ---- epilogue ----
    float sc;
    if (EPI == 1) {
        float s1 = fmaxf(g_stats[1] - g_stats[0], 1e-8f) / 255.0f;
        float s2 = fmaxf(g_stats[2], 1e-8f) / 127.0f;
        sc = s1 * s2;
    } else {
        float s1 = fmaxf(g_stats[5] - g_stats[4], 1e-8f) / 255.0f;
        float s2 = fmaxf(g_stats[3], 1e-8f) / 127.0f;
        sc = s1 * s2;
    }

    float lo = FBIG, hi = -FBIG;
#pragma unroll
    for (int j = 0; j < 4; j++) {
        int c = nBase + wn * 32 + j * 8 + 2 * t;
        float b0 = __ldg(bias + c), b1 = __ldg(bias + c + 1);
#pragma unroll
        for (int i = 0; i < 4; i++) {
            int row0 = mBase + wm * 64 + i * 16 + g;
            float v0 = sc * acc[i][j][0] + b0;
            float v1 = sc * acc[i][j][1] + b1;
            float v2 = sc * acc[i][j][2] + b0;
            float v3 = sc * acc[i][j][3] + b1;
            if (EPI == 1) { v0 = igelu(v0); v1 = igelu(v1); v2 = igelu(v2); v3 = igelu(v3); }
            if (row0 < Mn) {
                if (EPI == 1) {
                    lo = fminf(lo, fminf(v0, v1)); hi = fmaxf(hi, fmaxf(v0, v1));
                    __stcs((float2*)(C + (size_t)row0 * Nn + c), make_float2(v0, v1));
                } else {
                    *(float2*)(C + (size_t)row0 * Nn + c) = make_float2(v0, v1);
                }
            }
            if (row0 + 8 < Mn) {
                if (EPI == 1) {
                    lo = fminf(lo, fminf(v2, v3)); hi = fmaxf(hi, fmaxf(v2, v3));
                    __stcs((float2*)(C + (size_t)(row0 + 8) * Nn + c), make_float2(v2, v3));
                } else {
                    *(float2*)(C + (size_t)(row0 + 8) * Nn + c) = make_float2(v2, v3);
                }
            }
        }
    }

    if (EPI == 1) {
        for (int o = 16; o; o >>= 1) {
            lo = fminf(lo, __shfl_xor_sync(0xffffffffu, lo, o));
            hi = fmaxf(hi, __shfl_xor_sync(0xffffffffu, hi, o));
        }
        __shared__ float rlo[8], rhi[8];
        if (lane == 0) { rlo[warp] = lo; rhi[warp] = hi; }
        __syncthreads();
        if (tid == 0) {
            for (int i = 1; i < 8; i++) { lo = fminf(lo, rlo[i]); hi = fmaxf(hi, rhi[i]); }
            atomicMinF(&g_stats[4], lo);
            atomicMaxF(&g_stats[5], hi);
        }
    }
}

extern "C" void kernel_launch(void* const* d_in, const int* in_sizes, int n_in,
                              void* d_out, int out_size) {
    const float* x  = (const float*)d_in[0];
    const float* w1 = (const float*)d_in[1];
    const float* b1 = (const float*)d_in[2];
    const float* w2 = (const float*)d_in[3];
    const float* b2 = (const float*)d_in[4];
    float* out = (float*)d_out;

    constexpr int SMEM_BYTES = 3 * (128 + 128) * 128;   // 96 KB
    cudaFuncSetAttribute(k_gemm_bf<1>, cudaFuncAttributeMaxDynamicSharedMemorySize, SMEM_BYTES);
    cudaFuncSetAttribute(k_gemm_bf<2>, cudaFuncAttributeMaxDynamicSharedMemorySize, SMEM_BYTES);

    k_init<<<1, 1>>>();
    k_stats<<<XB + 2 * WB, 256>>>(x, w1, w2);
    k_quant<<<XB + 2 * WB, 256>>>(x, w1, w2);

    dim3 grid1((MT + 127) / 128, HH / 128);
    k_gemm_bf<1><<<grid1, 256, SMEM_BYTES>>>(b1, nullptr);

    k_quant_g<<<GB, 256>>>();

    dim3 grid2((MT + 127) / 128, DD / 128);
    k_gemm_bf<2><<<grid2, 256, SMEM_BYTES>>>(b2, out);
}

// round 11
// speedup vs baseline: 1.4872x; 1.4872x over previous
#include <cuda_runtime.h>
#include <cuda_bf16.h>
#include <cstdint>

#define DEVI static __device__ __forceinline__

static constexpr int MT = 64 * 197;   // 12608 rows
static constexpr int DD = 768;
static constexpr int HH = 3072;
static constexpr float FBIG = 3.0e38f;

// Scratch (allocation-free rule: __device__ globals)
__device__ __nv_bfloat16 g_xq[MT * DD];          // (q - zp) codes of x, exact ints in bf16
__device__ __nv_bfloat16 g_w1q[HH * DD];         // w1 codes
__device__ __nv_bfloat16 g_w2q[DD * HH];         // w2 codes
__device__ float         g_mid[(size_t)MT * HH]; // gelu output fp32
__device__ __nv_bfloat16 g_gq[(size_t)MT * HH];  // (q - zp) codes of g
__device__ float         g_stats[6];             // xmin,xmax,w1max,w2max,gmin,gmax

DEVI void atomicMinF(float* a, float v) {
    int* ai = (int*)a;
    int old = *ai;
    while (__int_as_float(old) > v) {
        int as = old;
        old = atomicCAS(ai, as, __float_as_int(v));
        if (old == as) break;
    }
}
DEVI void atomicMaxF(float* a, float v) {
    int* ai = (int*)a;
    int old = *ai;
    while (__int_as_float(old) < v) {
        int as = old;
        old = atomicCAS(ai, as, __float_as_int(v));
        if (old == as) break;
    }
}

__global__ void k_init() {
    g_stats[0] = FBIG;  g_stats[1] = -FBIG;
    g_stats[2] = 0.f;   g_stats[3] = 0.f;
    g_stats[4] = FBIG;  g_stats[5] = -FBIG;
}

// ---- fused stats: blocks [0,1024) minmax(x), [1024,1280) absmax(w1), [1280,1536) absmax(w2)
__global__ void k_stats(const float* __restrict__ x, const float* __restrict__ w1,
                        const float* __restrict__ w2) {
    int b = blockIdx.x;
    const float* src;
    int n4, nblk, b0, mode, sidx;
    if (b < 1024)      { src = x;  n4 = MT * DD / 4; nblk = 1024; b0 = 0;    mode = 0; sidx = 0; }
    else if (b < 1280) { src = w1; n4 = HH * DD / 4; nblk = 256;  b0 = 1024; mode = 1; sidx = 2; }
    else               { src = w2; n4 = DD * HH / 4; nblk = 256;  b0 = 1280; mode = 1; sidx = 3; }

    float lo = FBIG, hi = -FBIG;
    int st = nblk * blockDim.x;
    for (int i = (b - b0) * blockDim.x + threadIdx.x; i < n4; i += st) {
        float4 v = ((const float4*)src)[i];
        if (mode == 0) {
            lo = fminf(lo, fminf(fminf(v.x, v.y), fminf(v.z, v.w)));
            hi = fmaxf(hi, fmaxf(fmaxf(v.x, v.y), fmaxf(v.z, v.w)));
        } else {
            hi = fmaxf(hi, fmaxf(fmaxf(fabsf(v.x), fabsf(v.y)), fmaxf(fabsf(v.z), fabsf(v.w))));
        }
    }
    for (int o = 16; o; o >>= 1) {
        lo = fminf(lo, __shfl_xor_sync(0xffffffffu, lo, o));
        hi = fmaxf(hi, __shfl_xor_sync(0xffffffffu, hi, o));
    }
    __shared__ float slo[8], shi[8];
    int w = threadIdx.x >> 5;
    if ((threadIdx.x & 31) == 0) { slo[w] = lo; shi[w] = hi; }
    __syncthreads();
    if (threadIdx.x == 0) {
        for (int i = 1; i < 8; i++) { lo = fminf(lo, slo[i]); hi = fmaxf(hi, shi[i]); }
        if (mode == 0) { atomicMinF(&g_stats[0], lo); atomicMaxF(&g_stats[1], hi); }
        else           { atomicMaxF(&g_stats[sidx], hi); }
    }
}

DEVI float quant_act_one(float v, float s, float zp) {
    return fminf(fmaxf(rintf(v / s) + zp, 0.f), 255.f) - zp;
}

// ---- fused quant: blocks [0,2048) x, [2048,2560) w1, [2560,3072) w2
__global__ void k_quant(const float* __restrict__ x, const float* __restrict__ w1,
                        const float* __restrict__ w2) {
    int b = blockIdx.x;
    if (b < 2048) {
        float lo = g_stats[0], hi = g_stats[1];
        float s = fmaxf(hi - lo, 1e-8f) / 255.0f;
        float zp = rintf(-lo / s);
        __nv_bfloat162* qp = (__nv_bfloat162*)g_xq;
        int n4 = MT * DD / 4, st = 2048 * blockDim.x;
        for (int i = b * blockDim.x + threadIdx.x; i < n4; i += st) {
            float4 v = ((const float4*)x)[i];
            qp[2 * i]     = __floats2bfloat162_rn(quant_act_one(v.x, s, zp), quant_act_one(v.y, s, zp));
            qp[2 * i + 1] = __floats2bfloat162_rn(quant_act_one(v.z, s, zp), quant_act_one(v.w, s, zp));
        }
    } else {
        int which = (b >= 2560);
        const float* w = which ? w2 : w1;
        float s = fmaxf(g_stats[which ? 3 : 2], 1e-8f) / 127.0f;
        __nv_bfloat162* qp = (__nv_bfloat162*)(which ? g_w2q : g_w1q);
        int bb = b - (which ? 2560 : 2048);
        int n4 = HH * DD / 4, st = 512 * blockDim.x;
        for (int i = bb * blockDim.x + threadIdx.x; i < n4; i += st) {
            float4 v = ((const float4*)w)[i];
            float q0 = fminf(fmaxf(rintf(v.x / s), -128.f), 127.f);
            float q1 = fminf(fmaxf(rintf(v.y / s), -128.f), 127.f);
            float q2 = fminf(fmaxf(rintf(v.z / s), -128.f), 127.f);
            float q3 = fminf(fmaxf(rintf(v.w / s), -128.f), 127.f);
            qp[2 * i]     = __floats2bfloat162_rn(q0, q1);
            qp[2 * i + 1] = __floats2bfloat162_rn(q2, q3);
        }
    }
}

__global__ void k_quant_g(int n4) {
    float lo = g_stats[4], hi = g_stats[5];
    float s = fmaxf(hi - lo, 1e-8f) / 255.0f;
    float zp = rintf(-lo / s);
    __nv_bfloat162* qp = (__nv_bfloat162*)g_gq;
    const float4* x = (const float4*)g_mid;
    int st = gridDim.x * blockDim.x;
    for (int i = blockIdx.x * blockDim.x + threadIdx.x; i < n4; i += st) {
        float4 v = __ldcs(x + i);   // streaming read: mid is read-once
        qp[2 * i]     = __floats2bfloat162_rn(quant_act_one(v.x, s, zp), quant_act_one(v.y, s, zp));
        qp[2 * i + 1] = __floats2bfloat162_rn(quant_act_one(v.z, s, zp), quant_act_one(v.w, s, zp));
    }
}

DEVI float igelu(float x) {
    float tt = x * 0.70710678118654752440f;
    float at = fminf(fabsf(tt), 1.769f);
    float dd = at - 1.769f;
    float L = fmaf(-0.2888f, dd * dd, 1.0f);
    L = copysignf(L, tt);
    return x * 0.5f * (1.0f + L);
}

DEVI void ldsm_x4(uint32_t& r0, uint32_t& r1, uint32_t& r2, uint32_t& r3, uint32_t addr) {
    asm volatile("ldmatrix.sync.aligned.m8n8.x4.shared.b16 {%0,%1,%2,%3}, [%4];"
                 : "=r"(r0), "=r"(r1), "=r"(r2), "=r"(r3) : "r"(addr));
}
DEVI void hmma(float* c, const uint32_t* a, const uint32_t* b) {
    asm volatile(
        "mma.sync.aligned.m16n8k16.row.col.f32.bf16.bf16.f32 "
        "{%0,%1,%2,%3}, {%4,%5,%6,%7}, {%8,%9}, {%0,%1,%2,%3};\n"
        : "+f"(c[0]), "+f"(c[1]), "+f"(c[2]), "+f"(c[3])
        : "r"(a[0]), "r"(a[1]), "r"(a[2]), "r"(a[3]), "r"(b[0]), "r"(b[1]));
}

// ---------------------------------------------------------------------------
// bf16 GEMM: C[m,n] = sc * sum_k A[m,k]*B[n,k] + bias[n]
// BM=128, BN=128, BK=64, 256 threads, 3-stage cp.async ring, ldmatrix frags.
// Single __syncthreads per mainloop iteration.
// ---------------------------------------------------------------------------
template <int EPI>
__global__ void __launch_bounds__(256, 2) k_gemm_bf(const float* __restrict__ bias,
                                                    float* __restrict__ Cout) {
    constexpr int Mn = MT;
    constexpr int Nn = (EPI == 1) ? HH : DD;
    constexpr int Kn = (EPI == 1) ? DD : HH;
    constexpr int BM = 128, BN = 128, BK = 64;
    constexpr int KT = Kn / BK;
    constexpr uint32_t STAGE = (BM + BN) * 128;   // 32 KB

    const __nv_bfloat16* __restrict__ A = (EPI == 1) ? g_xq : g_gq;
    const __nv_bfloat16* __restrict__ B = (EPI == 1) ? g_w1q : g_w2q;
    float* __restrict__ C = (EPI == 1) ? g_mid : Cout;

    extern __shared__ char smem[];
    const uint32_t sbase = (uint32_t)__cvta_generic_to_shared(smem);

    const int tid = threadIdx.x;
    const int warp = tid >> 5, lane = tid & 31;
    const int wm = warp & 1, wn = warp >> 1;      // 2x4 warps, warp tile 64x32
    const int g = lane >> 2, t = lane & 3;
    const int mBase = blockIdx.x * BM, nBase = blockIdx.y * BN;

    float acc[4][4][4];
#pragma unroll
    for (int i = 0; i < 4; i++)
#pragma unroll
        for (int j = 0; j < 4; j++)
#pragma unroll
            for (int k = 0; k < 4; k++) acc[i][j][k] = 0.f;

    auto issue = [&](int s) {
        uint32_t sb = sbase + (uint32_t)(s % 3) * STAGE;
        const int kOff = s * BK;
#pragma unroll
        for (int ci = tid; ci < 2048; ci += 256) {
            int row = ci >> 3, c = ci & 7;
            uint32_t dst = sb + (uint32_t)(row * 128 + ((c ^ (row & 7)) << 4));
            if (row < BM) {
                int grow = mBase + row;
                bool ok = grow < Mn;
                int safe = ok ? grow : (Mn - 1);
                const __nv_bfloat16* gp = A + (size_t)safe * Kn + kOff + c * 8;
                int sz = ok ? 16 : 0;
                asm volatile("cp.async.cg.shared.global [%0], [%1], 16, %2;\n"
                             :: "r"(dst), "l"(gp), "r"(sz));
            } else {
                const __nv_bfloat16* gp = B + (size_t)(nBase + row - BM) * Kn + kOff + c * 8;
                asm volatile("cp.async.cg.shared.global [%0], [%1], 16, %2;\n"
                             :: "r"(dst), "l"(gp), "r"(16));
            }
        }
        asm volatile("cp.async.commit_group;\n");
    };

    auto compute = [&](int s) {
        uint32_t sa = sbase + (uint32_t)(s % 3) * STAGE;
        uint32_t sb = sa + (uint32_t)(BM * 128);
#pragma unroll
        for (int ks = 0; ks < 4; ks++) {
            uint32_t a[4][4], b[4][2];
#pragma unroll
            for (int i = 0; i < 4; i++) {
                int row = wm * 64 + i * 16 + (lane & 15);
                int chunk = 2 * ks + (lane >> 4);
                uint32_t addr = sa + (uint32_t)(row * 128 + ((chunk ^ (row & 7)) << 4));
                ldsm_x4(a[i][0], a[i][1], a[i][2], a[i][3], addr);
            }
#pragma unroll
            for (int jp = 0; jp < 2; jp++) {
                int q = lane >> 3;
                int nrow = wn * 32 + jp * 16 + (q >> 1) * 8 + (lane & 7);
                int chunk = 2 * ks + (q & 1);
                uint32_t addr = sb + (uint32_t)(nrow * 128 + ((chunk ^ (nrow & 7)) << 4));
                ldsm_x4(b[2 * jp][0], b[2 * jp][1], b[2 * jp + 1][0], b[2 * jp + 1][1], addr);
            }
#pragma unroll
            for (int i = 0; i < 4; i++)
#pragma unroll
                for (int j = 0; j < 4; j++) hmma(acc[i][j], a[i], b[j]);
        }
    };

    issue(0);
    issue(1);
    for (int kt = 0; kt < KT; kt++) {
        if (kt + 1 < KT) asm volatile("cp.async.wait_group 1;\n" ::: "memory");
        else             asm volatile("cp.async.wait_group 0;\n" ::: "memory");
        __syncthreads();
        if (kt + 2 < KT) issue(kt + 2);
        compute(kt);
    }

    // ---- epilogue ----
    float sc;
    if (EPI == 1) {
        float s1 = fmaxf(g_stats[1] - g_stats[0], 1e-8f) / 255.0f;
        float s2 = fmaxf(g_stats[2], 1e-8f) / 127.0f;
        sc = s1 * s2;
    } else {
        float s1 = fmaxf(g_stats[5] - g_stats[4], 1e-8f) / 255.0f;
        float s2 = fmaxf(g_stats[3], 1e-8f) / 127.0f;
        sc = s1 * s2;
    }

    float lo = FBIG, hi = -FBIG;
#pragma unroll
    for (int j = 0; j < 4; j++) {
        int c = nBase + wn * 32 + j * 8 + 2 * t;
        float b0 = __ldg(bias + c), b1 = __ldg(bias + c + 1);
#pragma unroll
        for (int i = 0; i < 4; i++) {
            int row0 = mBase + wm * 64 + i * 16 + g;
            float v0 = sc * acc[i][j][0] + b0;
            float v1 = sc * acc[i][j][1] + b1;
            float v2 = sc * acc[i][j][2] + b0;
            float v3 = sc * acc[i][j][3] + b1;
            if (EPI == 1) { v0 = igelu(v0); v1 = igelu(v1); v2 = igelu(v2); v3 = igelu(v3); }
            if (row0 < Mn) {
                if (EPI == 1) {
                    lo = fminf(lo, fminf(v0, v1)); hi = fmaxf(hi, fmaxf(v0, v1));
                    __stcs((float2*)(C + (size_t)row0 * Nn + c), make_float2(v0, v1));
                } else {
                    *(float2*)(C + (size_t)row0 * Nn + c) = make_float2(v0, v1);
                }
            }
            if (row0 + 8 < Mn) {
                if (EPI == 1) {
                    lo = fminf(lo, fminf(v2, v3)); hi = fmaxf(hi, fmaxf(v2, v3));
                    __stcs((float2*)(C + (size_t)(row0 + 8) * Nn + c), make_float2(v2, v3));
                } else {
                    *(float2*)(C + (size_t)(row0 + 8) * Nn + c) = make_float2(v2, v3);
                }
            }
        }
    }

    if (EPI == 1) {
        for (int o = 16; o; o >>= 1) {
            lo = fminf(lo, __shfl_xor_sync(0xffffffffu, lo, o));
            hi = fmaxf(hi, __shfl_xor_sync(0xffffffffu, hi, o));
        }
        __shared__ float rlo[8], rhi[8];
        if (lane == 0) { rlo[warp] = lo; rhi[warp] = hi; }
        __syncthreads();
        if (tid == 0) {
            for (int i = 1; i < 8; i++) { lo = fminf(lo, rlo[i]); hi = fmaxf(hi, rhi[i]); }
            atomicMinF(&g_stats[4], lo);
            atomicMaxF(&g_stats[5], hi);
        }
    }
}

extern "C" void kernel_launch(void* const* d_in, const int* in_sizes, int n_in,
                              void* d_out, int out_size) {
    const float* x  = (const float*)d_in[0];
    const float* w1 = (const float*)d_in[1];
    const float* b1 = (const float*)d_in[2];
    const float* w2 = (const float*)d_in[3];
    const float* b2 = (const float*)d_in[4];
    float* out = (float*)d_out;

    constexpr int SMEM_BYTES = 3 * (128 + 128) * 128;   // 96 KB
    cudaFuncSetAttribute(k_gemm_bf<1>, cudaFuncAttributeMaxDynamicSharedMemorySize, SMEM_BYTES);
    cudaFuncSetAttribute(k_gemm_bf<2>, cudaFuncAttributeMaxDynamicSharedMemorySize, SMEM_BYTES);

    k_init<<<1, 1>>>();
    k_stats<<<1536, 256>>>(x, w1, w2);
    k_quant<<<3072, 256>>>(x, w1, w2);

    dim3 grid1((MT + 127) / 128, HH / 128);
    k_gemm_bf<1><<<grid1, 256, SMEM_BYTES>>>(b1, nullptr);

    k_quant_g<<<4096, 256>>>((int)((size_t)MT * HH / 4));

    dim3 grid2((MT + 127) / 128, DD / 128);
    k_gemm_bf<2><<<grid2, 256, SMEM_BYTES>>>(b2, out);
}

// round 12
// speedup vs baseline: 1.5094x; 1.0149x over previous
#include <cuda_runtime.h>
#include <cuda_bf16.h>
#include <cstdint>

#define DEVI static __device__ __forceinline__

static constexpr int MT = 64 * 197;   // 12608 rows
static constexpr int DD = 768;
static constexpr int HH = 3072;
static constexpr float FBIG = 3.0e38f;

// quant_g exact grid: n4_g = MT*HH/4 = 9,682,944 = 4728*256*4*2
static constexpr int GB = 4728;

// Scratch (allocation-free rule: __device__ globals)
__device__ __nv_bfloat16 g_xq[MT * DD];          // (q - zp) codes of x, exact ints in bf16
__device__ __nv_bfloat16 g_w1q[HH * DD];         // w1 codes
__device__ __nv_bfloat16 g_w2q[DD * HH];         // w2 codes
__device__ float         g_mid[(size_t)MT * HH]; // gelu output fp32
__device__ __nv_bfloat16 g_gq[(size_t)MT * HH];  // (q - zp) codes of g
__device__ float         g_stats[6];             // xmin,xmax,w1max,w2max,gmin,gmax

DEVI void atomicMinF(float* a, float v) {
    int* ai = (int*)a;
    int old = *ai;
    while (__int_as_float(old) > v) {
        int as = old;
        old = atomicCAS(ai, as, __float_as_int(v));
        if (old == as) break;
    }
}
DEVI void atomicMaxF(float* a, float v) {
    int* ai = (int*)a;
    int old = *ai;
    while (__int_as_float(old) < v) {
        int as = old;
        old = atomicCAS(ai, as, __float_as_int(v));
        if (old == as) break;
    }
}

__global__ void k_init() {
    g_stats[0] = FBIG;  g_stats[1] = -FBIG;
    g_stats[2] = 0.f;   g_stats[3] = 0.f;
    g_stats[4] = FBIG;  g_stats[5] = -FBIG;
}

// ---- fused stats: blocks [0,1024) minmax(x), [1024,1280) absmax(w1), [1280,1536) absmax(w2)
__global__ void k_stats(const float* __restrict__ x, const float* __restrict__ w1,
                        const float* __restrict__ w2) {
    int b = blockIdx.x;
    const float* src;
    int n4, nblk, b0, mode, sidx;
    if (b < 1024)      { src = x;  n4 = MT * DD / 4; nblk = 1024; b0 = 0;    mode = 0; sidx = 0; }
    else if (b < 1280) { src = w1; n4 = HH * DD / 4; nblk = 256;  b0 = 1024; mode = 1; sidx = 2; }
    else               { src = w2; n4 = DD * HH / 4; nblk = 256;  b0 = 1280; mode = 1; sidx = 3; }

    float lo = FBIG, hi = -FBIG;
    int st = nblk * blockDim.x;
    for (int i = (b - b0) * blockDim.x + threadIdx.x; i < n4; i += st) {
        float4 v = ((const float4*)src)[i];
        if (mode == 0) {
            lo = fminf(lo, fminf(fminf(v.x, v.y), fminf(v.z, v.w)));
            hi = fmaxf(hi, fmaxf(fmaxf(v.x, v.y), fmaxf(v.z, v.w)));
        } else {
            hi = fmaxf(hi, fmaxf(fmaxf(fabsf(v.x), fabsf(v.y)), fmaxf(fabsf(v.z), fabsf(v.w))));
        }
    }
    for (int o = 16; o; o >>= 1) {
        lo = fminf(lo, __shfl_xor_sync(0xffffffffu, lo, o));
        hi = fmaxf(hi, __shfl_xor_sync(0xffffffffu, hi, o));
    }
    __shared__ float slo[8], shi[8];
    int w = threadIdx.x >> 5;
    if ((threadIdx.x & 31) == 0) { slo[w] = lo; shi[w] = hi; }
    __syncthreads();
    if (threadIdx.x == 0) {
        for (int i = 1; i < 8; i++) { lo = fminf(lo, slo[i]); hi = fmaxf(hi, shi[i]); }
        if (mode == 0) { atomicMinF(&g_stats[0], lo); atomicMaxF(&g_stats[1], hi); }
        else           { atomicMaxF(&g_stats[sidx], hi); }
    }
}

DEVI float quant_act_one(float v, float s, float zp) {
    return fminf(fmaxf(rintf(v / s) + zp, 0.f), 255.f) - zp;
}

// ---- fused quant: blocks [0,2048) x, [2048,2560) w1, [2560,3072) w2
__global__ void k_quant(const float* __restrict__ x, const float* __restrict__ w1,
                        const float* __restrict__ w2) {
    int b = blockIdx.x;
    if (b < 2048) {
        float lo = g_stats[0], hi = g_stats[1];
        float s = fmaxf(hi - lo, 1e-8f) / 255.0f;
        float zp = rintf(-lo / s);
        __nv_bfloat162* qp = (__nv_bfloat162*)g_xq;
        int n4 = MT * DD / 4, st = 2048 * blockDim.x;
        for (int i = b * blockDim.x + threadIdx.x; i < n4; i += st) {
            float4 v = ((const float4*)x)[i];
            qp[2 * i]     = __floats2bfloat162_rn(quant_act_one(v.x, s, zp), quant_act_one(v.y, s, zp));
            qp[2 * i + 1] = __floats2bfloat162_rn(quant_act_one(v.z, s, zp), quant_act_one(v.w, s, zp));
        }
    } else {
        int which = (b >= 2560);
        const float* w = which ? w2 : w1;
        float s = fmaxf(g_stats[which ? 3 : 2], 1e-8f) / 127.0f;
        __nv_bfloat162* qp = (__nv_bfloat162*)(which ? g_w2q : g_w1q);
        int bb = b - (which ? 2560 : 2048);
        int n4 = HH * DD / 4, st = 512 * blockDim.x;
        for (int i = bb * blockDim.x + threadIdx.x; i < n4; i += st) {
            float4 v = ((const float4*)w)[i];
            float q0 = fminf(fmaxf(rintf(v.x / s), -128.f), 127.f);
            float q1 = fminf(fmaxf(rintf(v.y / s), -128.f), 127.f);
            float q2 = fminf(fmaxf(rintf(v.z / s), -128.f), 127.f);
            float q3 = fminf(fmaxf(rintf(v.w / s), -128.f), 127.f);
            qp[2 * i]     = __floats2bfloat162_rn(q0, q1);
            qp[2 * i + 1] = __floats2bfloat162_rn(q2, q3);
        }
    }
}

DEVI uint2 quant_act4(float4 v, float s, float zp) {
    __nv_bfloat162 lo = __floats2bfloat162_rn(quant_act_one(v.x, s, zp), quant_act_one(v.y, s, zp));
    __nv_bfloat162 hi = __floats2bfloat162_rn(quant_act_one(v.z, s, zp), quant_act_one(v.w, s, zp));
    uint2 r;
    r.x = *(uint32_t*)&lo;
    r.y = *(uint32_t*)&hi;
    return r;
}

// ---- quant_g: ONLY kernel changed vs R11 — MLP=4, exact grid (GB=4728, 2 iters)
__global__ void k_quant_g() {
    float lo = g_stats[4], hi = g_stats[5];
    float s = fmaxf(hi - lo, 1e-8f) / 255.0f;
    float zp = rintf(-lo / s);
    uint2* qp = (uint2*)g_gq;
    const float4* src = (const float4*)g_mid;
    constexpr int n4 = (int)((size_t)MT * HH / 4);
    constexpr int st = GB * 256;
    int i = blockIdx.x * 256 + threadIdx.x;
#pragma unroll
    for (int o = 0; o < n4; o += 4 * st) {
        float4 a = __ldcs(src + i + o);
        float4 c = __ldcs(src + i + o + st);
        float4 d = __ldcs(src + i + o + 2 * st);
        float4 e = __ldcs(src + i + o + 3 * st);
        qp[i + o]          = quant_act4(a, s, zp);
        qp[i + o + st]     = quant_act4(c, s, zp);
        qp[i + o + 2 * st] = quant_act4(d, s, zp);
        qp[i + o + 3 * st] = quant_act4(e, s, zp);
    }
}

DEVI float igelu(float x) {
    float tt = x * 0.70710678118654752440f;
    float at = fminf(fabsf(tt), 1.769f);
    float dd = at - 1.769f;
    float L = fmaf(-0.2888f, dd * dd, 1.0f);
    L = copysignf(L, tt);
    return x * 0.5f * (1.0f + L);
}

DEVI void ldsm_x4(uint32_t& r0, uint32_t& r1, uint32_t& r2, uint32_t& r3, uint32_t addr) {
    asm volatile("ldmatrix.sync.aligned.m8n8.x4.shared.b16 {%0,%1,%2,%3}, [%4];"
                 : "=r"(r0), "=r"(r1), "=r"(r2), "=r"(r3) : "r"(addr));
}
DEVI void hmma(float* c, const uint32_t* a, const uint32_t* b) {
    asm volatile(
        "mma.sync.aligned.m16n8k16.row.col.f32.bf16.bf16.f32 "
        "{%0,%1,%2,%3}, {%4,%5,%6,%7}, {%8,%9}, {%0,%1,%2,%3};\n"
        : "+f"(c[0]), "+f"(c[1]), "+f"(c[2]), "+f"(c[3])
        : "r"(a[0]), "r"(a[1]), "r"(a[2]), "r"(a[3]), "r"(b[0]), "r"(b[1]));
}

// ---------------------------------------------------------------------------
// bf16 GEMM (R7/R11 config, UNCHANGED): BM=128, BN=128, BK=64, 256 threads,
// 2 CTA/SM, 3-stage cp.async ring, single __syncthreads per iteration.
// ---------------------------------------------------------------------------
template <int EPI>
__global__ void __launch_bounds__(256, 2) k_gemm_bf(const float* __restrict__ bias,
                                                    float* __restrict__ Cout) {
    constexpr int Mn = MT;
    constexpr int Nn = (EPI == 1) ? HH : DD;
    constexpr int Kn = (EPI == 1) ? DD : HH;
    constexpr int BM = 128, BN = 128, BK = 64;
    constexpr int KT = Kn / BK;
    constexpr uint32_t STAGE = (BM + BN) * 128;   // 32 KB

    const __nv_bfloat16* __restrict__ A = (EPI == 1) ? g_xq : g_gq;
    const __nv_bfloat16* __restrict__ B = (EPI == 1) ? g_w1q : g_w2q;
    float* __restrict__ C = (EPI == 1) ? g_mid : Cout;

    extern __shared__ char smem[];
    const uint32_t sbase = (uint32_t)__cvta_generic_to_shared(smem);

    const int tid = threadIdx.x;
    const int warp = tid >> 5, lane = tid & 31;
    const int wm = warp & 1, wn = warp >> 1;      // 2x4 warps, warp tile 64x32
    const int g = lane >> 2, t = lane & 3;
    const int mBase = blockIdx.x * BM, nBase = blockIdx.y * BN;

    float acc[4][4][4];
#pragma unroll
    for (int i = 0; i < 4; i++)
#pragma unroll
        for (int j = 0; j < 4; j++)
#pragma unroll
            for (int k = 0; k < 4; k++) acc[i][j][k] = 0.f;

    auto issue = [&](int s) {
        uint32_t sb = sbase + (uint32_t)(s % 3) * STAGE;
        const int kOff = s * BK;
#pragma unroll
        for (int ci = tid; ci < 2048; ci += 256) {
            int row = ci >> 3, c = ci & 7;
            uint32_t dst = sb + (uint32_t)(row * 128 + ((c ^ (row & 7)) << 4));
            if (row < BM) {
                int grow = mBase + row;
                bool ok = grow < Mn;
                int safe = ok ? grow : (Mn - 1);
                const __nv_bfloat16* gp = A + (size_t)safe * Kn + kOff + c * 8;
                int sz = ok ? 16 : 0;
                asm volatile("cp.async.cg.shared.global [%0], [%1], 16, %2;\n"
                             :: "r"(dst), "l"(gp), "r"(sz));
            } else {
                const __nv_bfloat16* gp = B + (size_t)(nBase + row - BM) * Kn + kOff + c * 8;
                asm volatile("cp.async.cg.shared.global [%0], [%1], 16, %2;\n"
                             :: "r"(dst), "l"(gp), "r"(16));
            }
        }
        asm volatile("cp.async.commit_group;\n");
    };

    auto compute = [&](int s) {
        uint32_t sa = sbase + (uint32_t)(s % 3) * STAGE;
        uint32_t sb = sa + (uint32_t)(BM * 128);
#pragma unroll
        for (int ks = 0; ks < 4; ks++) {
            uint32_t a[4][4], b[4][2];
#pragma unroll
            for (int i = 0; i < 4; i++) {
                int row = wm * 64 + i * 16 + (lane & 15);
                int chunk = 2 * ks + (lane >> 4);
                uint32_t addr = sa + (uint32_t)(row * 128 + ((chunk ^ (row & 7)) << 4));
                ldsm_x4(a[i][0], a[i][1], a[i][2], a[i][3], addr);
            }
#pragma unroll
            for (int jp = 0; jp < 2; jp++) {
                int q = lane >> 3;
                int nrow = wn * 32 + jp * 16 + (q >> 1) * 8 + (lane & 7);
                int chunk = 2 * ks + (q & 1);
                uint32_t addr = sb + (uint32_t)(nrow * 128 + ((chunk ^ (nrow & 7)) << 4));
                ldsm_x4(b[2 * jp][0], b[2 * jp][1], b[2 * jp + 1][0], b[2 * jp + 1][1], addr);
            }
#pragma unroll
            for (int i = 0; i < 4; i++)
#pragma unroll
                for (int j = 0; j < 4; j++) hmma(acc[i][j], a[i], b[j]);
        }
    };

    issue(0);
    issue(1);
    for (int kt = 0; kt < KT; kt++) {
        if (kt + 1 < KT) asm volatile("cp.async.wait_group 1;\n" ::: "memory");
        else             asm volatile("cp.async.wait_group 0;\n" ::: "memory");
        __syncthreads();
        if (kt + 2 < KT) issue(kt + 2);
        compute(kt);
    }

    // ---- epilogue ----
    float sc;
    if (EPI == 1) {
        float s1 = fmaxf(g_stats[1] - g_stats[0], 1e-8f) / 255.0f;
        float s2 = fmaxf(g_stats[2], 1e-8f) / 127.0f;
        sc = s1 * s2;
    } else {
        float s1 = fmaxf(g_stats[5] - g_stats[4], 1e-8f) / 255.0f;
        float s2 = fmaxf(g_stats[3], 1e-8f) / 127.0f;
        sc = s1 * s2;
    }

    float lo = FBIG, hi = -FBIG;
#pragma unroll
    for (int j = 0; j < 4; j++) {
        int c = nBase + wn * 32 + j * 8 + 2 * t;
        float b0 = __ldg(bias + c), b1 = __ldg(bias + c + 1);
#pragma unroll
        for (int i = 0; i < 4; i++) {
            int row0 = mBase + wm * 64 + i * 16 + g;
            float v0 = sc * acc[i][j][0] + b0;
            float v1 = sc * acc[i][j][1] + b1;
            float v2 = sc * acc[i][j][2] + b0;
            float v3 = sc * acc[i][j][3] + b1;
            if (EPI == 1) { v0 = igelu(v0); v1 = igelu(v1); v2 = igelu(v2); v3 = igelu(v3); }
            if (row0 < Mn) {
                if (EPI == 1) {
                    lo = fminf(lo, fminf(v0, v1)); hi = fmaxf(hi, fmaxf(v0, v1));
                    __stcs((float2*)(C + (size_t)row0 * Nn + c), make_float2(v0, v1));
                } else {
                    *(float2*)(C + (size_t)row0 * Nn + c) = make_float2(v0, v1);
                }
            }
            if (row0 + 8 < Mn) {
                if (EPI == 1) {
                    lo = fminf(lo, fminf(v2, v3)); hi = fmaxf(hi, fmaxf(v2, v3));
                    __stcs((float2*)(C + (size_t)(row0 + 8) * Nn + c), make_float2(v2, v3));
                } else {
                    *(float2*)(C + (size_t)(row0 + 8) * Nn + c) = make_float2(v2, v3);
                }
            }
        }
    }

    if (EPI == 1) {
        for (int o = 16; o; o >>= 1) {
            lo = fminf(lo, __shfl_xor_sync(0xffffffffu, lo, o));
            hi = fmaxf(hi, __shfl_xor_sync(0xffffffffu, hi, o));
        }
        __shared__ float rlo[8], rhi[8];
        if (lane == 0) { rlo[warp] = lo; rhi[warp] = hi; }
        __syncthreads();
        if (tid == 0) {
            for (int i = 1; i < 8; i++) { lo = fminf(lo, rlo[i]); hi = fmaxf(hi, rhi[i]); }
            atomicMinF(&g_stats[4], lo);
            atomicMaxF(&g_stats[5], hi);
        }
    }
}

extern "C" void kernel_launch(void* const* d_in, const int* in_sizes, int n_in,
                              void* d_out, int out_size) {
    const float* x  = (const float*)d_in[0];
    const float* w1 = (const float*)d_in[1];
    const float* b1 = (const float*)d_in[2];
    const float* w2 = (const float*)d_in[3];
    const float* b2 = (const float*)d_in[4];
    float* out = (float*)d_out;

    constexpr int SMEM_BYTES = 3 * (128 + 128) * 128;   // 96 KB
    cudaFuncSetAttribute(k_gemm_bf<1>, cudaFuncAttributeMaxDynamicSharedMemorySize, SMEM_BYTES);
    cudaFuncSetAttribute(k_gemm_bf<2>, cudaFuncAttributeMaxDynamicSharedMemorySize, SMEM_BYTES);

    k_init<<<1, 1>>>();
    k_stats<<<1536, 256>>>(x, w1, w2);
    k_quant<<<3072, 256>>>(x, w1, w2);

    dim3 grid1((MT + 127) / 128, HH / 128);
    k_gemm_bf<1><<<grid1, 256, SMEM_BYTES>>>(b1, nullptr);

    k_quant_g<<<GB, 256>>>();

    dim3 grid2((MT + 127) / 128, DD / 128);
    k_gemm_bf<2><<<grid2, 256, SMEM_BYTES>>>(b2, out);
}